// round 1
// baseline (speedup 1.0000x reference)
#include <cuda_runtime.h>
#include <cuda_bf16.h>
#include <cstdint>

// NeRF volume rendering: warp-per-ray, 2 samples per lane (N=64).
// rgb:   (R, 64, 3) float32
// sigma: (R, 64)    float32  (trailing 1-dim collapsed)
// t:     (R, 64)    float32  (sorted)
// out:   image (R,3) | depth (R) | weights (R,64)

#define FULL_MASK 0xffffffffu

__global__ void __launch_bounds__(256) nerf_render_kernel(
    const float* __restrict__ rgb,
    const float* __restrict__ sigma,
    const float* __restrict__ t_vals,
    float* __restrict__ image,
    float* __restrict__ depth,
    float* __restrict__ weights,
    int n_rays)
{
    const int gtid = blockIdx.x * blockDim.x + threadIdx.x;
    const int ray  = gtid >> 5;
    if (ray >= n_rays) return;
    const int lane = threadIdx.x & 31;

    // --- coalesced float2 loads: lane l owns samples 2l, 2l+1 ---
    const float2 tv = __ldg(((const float2*)t_vals) + (size_t)ray * 32 + lane);
    const float2 sg = __ldg(((const float2*)sigma)  + (size_t)ray * 32 + lane);

    // deltas: d0 = t[2l+1]-t[2l]; d1 = t[2l+2]-t[2l+1] (next lane's tv.x),
    // lane 31 sample 63 gets the FAR_DELTA sentinel.
    const float t_next = __shfl_down_sync(FULL_MASK, tv.x, 1);
    const float d0 = tv.y - tv.x;
    const float d1 = (lane == 31) ? 1e10f : (t_next - tv.y);

    // alpha and exp_term (match reference: exp_term = 1 - alpha)
    const float a0 = 1.0f - __expf(-sg.x * d0);
    const float a1 = 1.0f - __expf(-sg.y * d1);
    const float e0 = (1.0f - a0) + 1e-10f;
    const float e1 = (1.0f - a1) + 1e-10f;

    // --- exclusive cumprod across 64 samples ---
    // per-lane pair product, inclusive warp scan (multiply), then shift.
    float inc = e0 * e1;
    #pragma unroll
    for (int off = 1; off < 32; off <<= 1) {
        const float x = __shfl_up_sync(FULL_MASK, inc, off);
        if (lane >= off) inc *= x;
    }
    float exc = __shfl_up_sync(FULL_MASK, inc, 1);
    if (lane == 0) exc = 1.0f;

    const float T0 = exc;        // transmittance before sample 2l
    const float T1 = exc * e0;   // before sample 2l+1
    const float w0 = a0 * T0;
    const float w1 = a1 * T1;

    // coalesced weights store
    ((float2*)weights)[(size_t)ray * 32 + lane] = make_float2(w0, w1);

    // --- rgb accumulation: lane reads its 6 contiguous floats ---
    const float* rg = rgb + (size_t)ray * 192 + lane * 6;
    float r = w0 * __ldg(rg + 0) + w1 * __ldg(rg + 3);
    float g = w0 * __ldg(rg + 1) + w1 * __ldg(rg + 4);
    float b = w0 * __ldg(rg + 2) + w1 * __ldg(rg + 5);
    float dep = w0 * tv.x + w1 * tv.y;

    // warp tree-reduce (sum) for the 4 accumulators
    #pragma unroll
    for (int off = 16; off > 0; off >>= 1) {
        r   += __shfl_xor_sync(FULL_MASK, r,   off);
        g   += __shfl_xor_sync(FULL_MASK, g,   off);
        b   += __shfl_xor_sync(FULL_MASK, b,   off);
        dep += __shfl_xor_sync(FULL_MASK, dep, off);
    }

    if (lane == 0) {
        image[(size_t)ray * 3 + 0] = r;
        image[(size_t)ray * 3 + 1] = g;
        image[(size_t)ray * 3 + 2] = b;
        depth[ray] = dep;
    }
}

extern "C" void kernel_launch(void* const* d_in, const int* in_sizes, int n_in,
                              void* d_out, int out_size)
{
    const float* rgb    = (const float*)d_in[0];
    const float* sigma  = (const float*)d_in[1];
    const float* t_vals = (const float*)d_in[2];

    const int n_rays = in_sizes[2] / 64;   // t_vals element count / N

    float* out     = (float*)d_out;
    float* image   = out;                       // n_rays * 3
    float* depth   = out + (size_t)n_rays * 3;  // n_rays
    float* weights = depth + n_rays;            // n_rays * 64

    // 256 threads = 8 warps = 8 rays per block
    const int blocks = (n_rays + 7) / 8;
    nerf_render_kernel<<<blocks, 256>>>(rgb, sigma, t_vals,
                                        image, depth, weights, n_rays);
}

// round 3
// speedup vs baseline: 1.0071x; 1.0071x over previous
#include <cuda_runtime.h>
#include <cuda_bf16.h>
#include <cstdint>

// NeRF volume rendering: warp-per-ray, 2 samples per lane (N=64).
// rgb:   (R, 64, 3) float32
// sigma: (R, 64)    float32  (trailing 1-dim collapsed)
// t:     (R, 64)    float32  (sorted)
// out:   image (R,3) | depth (R) | weights (R,64)

#define FULL_MASK 0xffffffffu

__global__ void __launch_bounds__(256) nerf_render_kernel(
    const float* __restrict__ rgb,
    const float* __restrict__ sigma,
    const float* __restrict__ t_vals,
    float* __restrict__ image,
    float* __restrict__ depth,
    float* __restrict__ weights,
    int n_rays)
{
    const int gtid = blockIdx.x * blockDim.x + threadIdx.x;
    const int ray  = gtid >> 5;
    if (ray >= n_rays) return;
    const int lane = threadIdx.x & 31;

    // --- coalesced float2 loads: lane l owns samples 2l, 2l+1 ---
    const float2 tv = __ldg(((const float2*)t_vals) + (size_t)ray * 32 + lane);
    const float2 sg = __ldg(((const float2*)sigma)  + (size_t)ray * 32 + lane);

    // deltas: d0 = t[2l+1]-t[2l]; d1 = t[2l+2]-t[2l+1] (next lane's tv.x),
    // lane 31 sample 63 gets the FAR_DELTA sentinel.
    const float t_next = __shfl_down_sync(FULL_MASK, tv.x, 1);
    const float d0 = tv.y - tv.x;
    const float d1 = (lane == 31) ? 1e10f : (t_next - tv.y);

    // alpha and exp_term (match reference: exp_term = 1 - alpha)
    const float a0 = 1.0f - __expf(-sg.x * d0);
    const float a1 = 1.0f - __expf(-sg.y * d1);
    const float e0 = (1.0f - a0) + 1e-10f;
    const float e1 = (1.0f - a1) + 1e-10f;

    // --- exclusive cumprod across 64 samples ---
    // per-lane pair product, inclusive warp scan (multiply), then shift.
    float inc = e0 * e1;
    #pragma unroll
    for (int off = 1; off < 32; off <<= 1) {
        const float x = __shfl_up_sync(FULL_MASK, inc, off);
        if (lane >= off) inc *= x;
    }
    float exc = __shfl_up_sync(FULL_MASK, inc, 1);
    if (lane == 0) exc = 1.0f;

    const float T0 = exc;        // transmittance before sample 2l
    const float T1 = exc * e0;   // before sample 2l+1
    const float w0 = a0 * T0;
    const float w1 = a1 * T1;

    // coalesced weights store
    ((float2*)weights)[(size_t)ray * 32 + lane] = make_float2(w0, w1);

    // --- rgb accumulation: lane reads its 6 contiguous floats ---
    const float* rg = rgb + (size_t)ray * 192 + lane * 6;
    float r = w0 * __ldg(rg + 0) + w1 * __ldg(rg + 3);
    float g = w0 * __ldg(rg + 1) + w1 * __ldg(rg + 4);
    float b = w0 * __ldg(rg + 2) + w1 * __ldg(rg + 5);
    float dep = w0 * tv.x + w1 * tv.y;

    // warp tree-reduce (sum) for the 4 accumulators
    #pragma unroll
    for (int off = 16; off > 0; off >>= 1) {
        r   += __shfl_xor_sync(FULL_MASK, r,   off);
        g   += __shfl_xor_sync(FULL_MASK, g,   off);
        b   += __shfl_xor_sync(FULL_MASK, b,   off);
        dep += __shfl_xor_sync(FULL_MASK, dep, off);
    }

    if (lane == 0) {
        image[(size_t)ray * 3 + 0] = r;
        image[(size_t)ray * 3 + 1] = g;
        image[(size_t)ray * 3 + 2] = b;
        depth[ray] = dep;
    }
}

extern "C" void kernel_launch(void* const* d_in, const int* in_sizes, int n_in,
                              void* d_out, int out_size)
{
    const float* rgb    = (const float*)d_in[0];
    const float* sigma  = (const float*)d_in[1];
    const float* t_vals = (const float*)d_in[2];

    const int n_rays = in_sizes[2] / 64;   // t_vals element count / N

    float* out     = (float*)d_out;
    float* image   = out;                       // n_rays * 3
    float* depth   = out + (size_t)n_rays * 3;  // n_rays
    float* weights = depth + n_rays;            // n_rays * 64

    // 256 threads = 8 warps = 8 rays per block
    const int blocks = (n_rays + 7) / 8;
    nerf_render_kernel<<<blocks, 256>>>(rgb, sigma, t_vals,
                                        image, depth, weights, n_rays);
}